// round 14
// baseline (speedup 1.0000x reference)
#include <cuda_runtime.h>

typedef unsigned long long ull;

#define S_LEN 2048
#define COLS 1024

__device__ float g_xg[(size_t)32 * S_LEN * COLS];   // [b*S+s][gate*256+j], gates f,i,c,o

__device__ __forceinline__ ull fma2(ull a, ull b, ull c){
  ull d; asm("fma.rn.f32x2 %0, %1, %2, %3;" : "=l"(d) : "l"(a), "l"(b), "l"(c)); return d;
}
__device__ __forceinline__ ull dup2(float x){
  ull d; asm("mov.b64 %0, {%1, %1};" : "=l"(d) : "f"(x)); return d;
}
__device__ __forceinline__ ull pack2(float lo, float hi){
  ull d; asm("mov.b64 %0, {%1, %2};" : "=l"(d) : "f"(lo), "f"(hi)); return d;
}
__device__ __forceinline__ void unpack2(ull v, float& lo, float& hi){
  asm("mov.b64 {%0, %1}, %2;" : "=f"(lo), "=f"(hi) : "l"(v));
}
__device__ __forceinline__ float sigmoidf_(float x){ return 1.f / (1.f + __expf(-x)); }
__device__ __forceinline__ unsigned smem_u32(const void* p){
  unsigned a; asm("{ .reg .u64 t; cvta.to.shared.u64 t, %1; cvt.u32.u64 %0, t; }" : "=r"(a) : "l"(p));
  return a;
}
__device__ __forceinline__ void st_cluster_f32(unsigned laddr, unsigned rank, float v){
  asm volatile("{ .reg .b32 ra; mapa.shared::cluster.u32 ra, %0, %1; "
               "st.shared::cluster.f32 [ra], %2; }" :: "r"(laddr), "r"(rank), "f"(v) : "memory");
}
// remote arrive with cluster-scope release (publishes all writes happens-before it)
__device__ __forceinline__ void arrive_rank(unsigned local_mbar, unsigned rank){
  asm volatile("{ .reg .b32 ra; mapa.shared::cluster.u32 ra, %0, %1; "
               "mbarrier.arrive.release.cluster.shared::cluster.b64 _, [ra]; }"
               :: "r"(local_mbar), "r"(rank) : "memory");
}
#define WAITP(mbar, par) do { \
  asm volatile("{\n\t.reg .pred P1;\n\tWL%=:\n\t" \
    "mbarrier.try_wait.parity.acquire.cluster.shared::cta.b64 P1, [%0], %1, 0x989680;\n\t" \
    "@P1 bra.uni WD%=;\n\tbra.uni WL%=;\n\tWD%=:\n\t}" \
    :: "r"(mbar), "r"(par) : "memory"); \
} while(0)

// ---------------- kernel 1: xg = x @ W + b (fp32x2 GEMM, 128x64x32 tiles) ----------------
__global__ __launch_bounds__(256, 2) void xw_gemm(
    const float* __restrict__ x,
    const float* __restrict__ Wf, const float* __restrict__ Wi,
    const float* __restrict__ Wc, const float* __restrict__ Wo,
    const float* __restrict__ bf, const float* __restrict__ bi,
    const float* __restrict__ bc, const float* __restrict__ bo)
{
  __shared__ float A_s[32][132];
  __shared__ float B_s[32][68];
  const int r0 = blockIdx.x * 128;
  const int c0 = blockIdx.y * 64;
  const int gate = c0 >> 8, j0 = c0 & 255;
  const float* Wg; const float* bg;
  if (gate == 0){ Wg = Wf; bg = bf; } else if (gate == 1){ Wg = Wi; bg = bi; }
  else if (gate == 2){ Wg = Wc; bg = bc; } else { Wg = Wo; bg = bo; }

  const int tid = threadIdx.x;
  const int tx = tid & 15, ty = tid >> 4;
  const int arow = tid >> 3, ak = (tid & 7) * 4;

  ull acc[4][4];
  #pragma unroll
  for (int i = 0; i < 4; i++)
    #pragma unroll
    for (int j = 0; j < 4; j++) acc[i][j] = 0ull;

  for (int kc = 0; kc < 256; kc += 32){
    #pragma unroll
    for (int i = 0; i < 4; i++){
      float4 v = *(const float4*)&x[(size_t)(r0 + arow + i*32) * 256 + kc + ak];
      A_s[ak+0][arow + i*32] = v.x; A_s[ak+1][arow + i*32] = v.y;
      A_s[ak+2][arow + i*32] = v.z; A_s[ak+3][arow + i*32] = v.w;
    }
    #pragma unroll
    for (int j = 0; j < 2; j++){
      int e = tid + j*256, kk = e >> 4, nn = (e & 15) * 4;
      *(float4*)&B_s[kk][nn] = *(const float4*)&Wg[(size_t)(kc + kk) * 256 + j0 + nn];
    }
    __syncthreads();
    #pragma unroll
    for (int k = 0; k < 32; k++){
      ulonglong2 a01 = *(const ulonglong2*)&A_s[k][ty*8];
      ulonglong2 a23 = *(const ulonglong2*)&A_s[k][ty*8 + 4];
      float4 bq = *(const float4*)&B_s[k][tx*4];
      ull bb0 = dup2(bq.x), bb1 = dup2(bq.y), bb2 = dup2(bq.z), bb3 = dup2(bq.w);
      ull av[4] = {a01.x, a01.y, a23.x, a23.y};
      #pragma unroll
      for (int i = 0; i < 4; i++){
        acc[i][0] = fma2(av[i], bb0, acc[i][0]);
        acc[i][1] = fma2(av[i], bb1, acc[i][1]);
        acc[i][2] = fma2(av[i], bb2, acc[i][2]);
        acc[i][3] = fma2(av[i], bb3, acc[i][3]);
      }
    }
    __syncthreads();
  }

  float bias[4];
  #pragma unroll
  for (int j = 0; j < 4; j++) bias[j] = bg[j0 + tx*4 + j];
  #pragma unroll
  for (int i = 0; i < 4; i++){
    float lo[4], hi[4];
    #pragma unroll
    for (int j = 0; j < 4; j++) unpack2(acc[i][j], lo[j], hi[j]);
    size_t base = (size_t)(r0 + ty*8 + 2*i) * COLS + c0 + tx*4;
    *(float4*)&g_xg[base]        = make_float4(lo[0]+bias[0], lo[1]+bias[1], lo[2]+bias[2], lo[3]+bias[3]);
    *(float4*)&g_xg[base + COLS] = make_float4(hi[0]+bias[0], hi[1]+bias[1], hi[2]+bias[2], hi[3]+bias[3]);
  }
}

// ---------------- kernel 2: interleaved two-chain clustered recurrence ----------------
// 128 CTAs = 16 clusters x 8 CTAs. Each cluster runs TWO independent 1-batch
// chains (A,B), alternating, with separate mbarrier cluster barriers so each
// barrier's settle latency is hidden behind the other chain's compute.
// CTA owns units [r*32, r*32+32) x 4 gates; U register-resident.
__global__ __launch_bounds__(256, 1) __cluster_dims__(8, 1, 1)
void lstm_rec(
    const float* __restrict__ Uf, const float* __restrict__ Ui,
    const float* __restrict__ Uc, const float* __restrict__ Uo,
    float* __restrict__ out, int out_size)
{
  __shared__ __align__(16) float hA[2][256];
  __shared__ __align__(16) float hB[2][256];
  __shared__ __align__(16) float red[8][128];   // [k-slice][unit*4 + gate]
  __shared__ __align__(8)  ull mb[2];           // mbarriers: [0]=A, [1]=B

  const int tid = threadIdx.x;
  const int w = tid >> 5, lane = tid & 31;
  const int r = blockIdx.x & 7;      // cluster rank
  const int q = blockIdx.x >> 3;     // cluster id 0..15
  const int bA = q * 2, bB = q * 2 + 1;
  const int ju = r * 32 + lane;      // owned unit (per gate)
  const int kb = w * 32;             // owned k-chunk

  // U slice -> registers: ur[gate][jj] covers k in [kb+4jj, kb+4jj+4), col ju
  ulonglong2 ur[4][8];
  #pragma unroll
  for (int g = 0; g < 4; g++){
    const float* Ug = (g == 0) ? Uf : (g == 1) ? Ui : (g == 2) ? Uc : Uo;
    #pragma unroll
    for (int jj = 0; jj < 8; jj++){
      int k0 = kb + jj * 4;
      float a0 = __ldg(&Ug[(size_t)(k0 + 0) * 256 + ju]);
      float a1 = __ldg(&Ug[(size_t)(k0 + 1) * 256 + ju]);
      float a2 = __ldg(&Ug[(size_t)(k0 + 2) * 256 + ju]);
      float a3 = __ldg(&Ug[(size_t)(k0 + 3) * 256 + ju]);
      ur[g][jj].x = pack2(a0, a1);
      ur[g][jj].y = pack2(a2, a3);
    }
  }

  // zero h buffers; init mbarriers (count = 8 arrivals, one per cluster CTA)
  for (int e = tid; e < 512; e += 256){ ((float*)hA)[e] = 0.f; ((float*)hB)[e] = 0.f; }
  const unsigned mbA = smem_u32(&mb[0]), mbB = smem_u32(&mb[1]);
  if (tid == 0){
    asm volatile("mbarrier.init.shared.b64 [%0], %1;" :: "r"(mbA), "r"(8) : "memory");
    asm volatile("mbarrier.init.shared.b64 [%0], %1;" :: "r"(mbB), "r"(8) : "memory");
  }
  __syncthreads();
  asm volatile("barrier.cluster.arrive.aligned;" ::: "memory");
  asm volatile("barrier.cluster.wait.aligned;"   ::: "memory");
  // pre-complete phase 0 of both chains (h[0] is locally zeroed; no data dep)
  if (tid < 8){ arrive_rank(mbA, (unsigned)tid); arrive_rank(mbB, (unsigned)tid); }

  const unsigned hAa = smem_u32(hA), hBa = smem_u32(hB);
  float cstA = 0.f, hlA = 0.f, cstB = 0.f, hlB = 0.f;

  for (int s = 0; s < S_LEN; s++){
    const int p = s & 1, pn = p ^ 1;
    const unsigned par = (unsigned)(s & 1);

    // ======== chain A ========
    float xg0, xg1, xg2, xg3;
    if (w == 0){
      const float* xp = &g_xg[((size_t)bA * S_LEN + s) * COLS + ju];
      xg0 = __ldg(xp); xg1 = __ldg(xp + 256); xg2 = __ldg(xp + 512); xg3 = __ldg(xp + 768);
    }
    WAITP(mbA, par);
    {
      ull acc[4] = {0ull, 0ull, 0ull, 0ull};
      #pragma unroll
      for (int jj = 0; jj < 8; jj++){
        ulonglong2 hv = *(const ulonglong2*)&hA[p][kb + jj*4];
        #pragma unroll
        for (int g = 0; g < 4; g++){
          acc[g] = fma2(hv.x, ur[g][jj].x, acc[g]);
          acc[g] = fma2(hv.y, ur[g][jj].y, acc[g]);
        }
      }
      float rs[4];
      #pragma unroll
      for (int g = 0; g < 4; g++){ float lo, hi; unpack2(acc[g], lo, hi); rs[g] = lo + hi; }
      *(float4*)&red[w][lane*4] = make_float4(rs[0], rs[1], rs[2], rs[3]);
    }
    __syncthreads();
    if (w == 0){
      float z0 = xg0, z1 = xg1, z2 = xg2, z3 = xg3;
      #pragma unroll
      for (int ww = 0; ww < 8; ww++){
        float4 rv = *(const float4*)&red[ww][lane*4];
        z0 += rv.x; z1 += rv.y; z2 += rv.z; z3 += rv.w;
      }
      float f  = sigmoidf_(z0);
      float ii = sigmoidf_(z1);
      float gg = tanhf(z2);
      float oo = sigmoidf_(z3);
      cstA = f * cstA + ii * gg;
      hlA = oo * tanhf(cstA);
      unsigned haddr = hAa + (unsigned)((pn*256 + ju) * 4);
      #pragma unroll
      for (int t = 0; t < 8; t++) st_cluster_f32(haddr, (unsigned)t, hlA);
      out[((size_t)bA * S_LEN + s) * 256 + ju] = hlA;
    }
    __syncthreads();                       // pushes happen-before the arrives below
    if (tid < 8) arrive_rank(mbA, (unsigned)tid);

    // ======== chain B (overlaps chain A's barrier settle) ========
    if (w == 0){
      const float* xp = &g_xg[((size_t)bB * S_LEN + s) * COLS + ju];
      xg0 = __ldg(xp); xg1 = __ldg(xp + 256); xg2 = __ldg(xp + 512); xg3 = __ldg(xp + 768);
    }
    WAITP(mbB, par);
    {
      ull acc[4] = {0ull, 0ull, 0ull, 0ull};
      #pragma unroll
      for (int jj = 0; jj < 8; jj++){
        ulonglong2 hv = *(const ulonglong2*)&hB[p][kb + jj*4];
        #pragma unroll
        for (int g = 0; g < 4; g++){
          acc[g] = fma2(hv.x, ur[g][jj].x, acc[g]);
          acc[g] = fma2(hv.y, ur[g][jj].y, acc[g]);
        }
      }
      float rs[4];
      #pragma unroll
      for (int g = 0; g < 4; g++){ float lo, hi; unpack2(acc[g], lo, hi); rs[g] = lo + hi; }
      *(float4*)&red[w][lane*4] = make_float4(rs[0], rs[1], rs[2], rs[3]);
    }
    __syncthreads();
    if (w == 0){
      float z0 = xg0, z1 = xg1, z2 = xg2, z3 = xg3;
      #pragma unroll
      for (int ww = 0; ww < 8; ww++){
        float4 rv = *(const float4*)&red[ww][lane*4];
        z0 += rv.x; z1 += rv.y; z2 += rv.z; z3 += rv.w;
      }
      float f  = sigmoidf_(z0);
      float ii = sigmoidf_(z1);
      float gg = tanhf(z2);
      float oo = sigmoidf_(z3);
      cstB = f * cstB + ii * gg;
      hlB = oo * tanhf(cstB);
      unsigned haddr = hBa + (unsigned)((pn*256 + ju) * 4);
      #pragma unroll
      for (int t = 0; t < 8; t++) st_cluster_f32(haddr, (unsigned)t, hlB);
      out[((size_t)bB * S_LEN + s) * 256 + ju] = hlB;
    }
    __syncthreads();
    if (tid < 8) arrive_rank(mbB, (unsigned)tid);
  }

  // final (h_T, c_T), appended after hidden_seq if the output carries them
  if (w == 0 && out_size >= 16777216 + 16384){
    size_t baseA = (size_t)16777216 + (size_t)bA * 256 + ju;
    size_t baseB = (size_t)16777216 + (size_t)bB * 256 + ju;
    out[baseA]        = hlA;
    out[baseA + 8192] = cstA;
    out[baseB]        = hlB;
    out[baseB + 8192] = cstB;
  }

  // no CTA may exit while peers might still push into its smem
  asm volatile("barrier.cluster.arrive.aligned;" ::: "memory");
  asm volatile("barrier.cluster.wait.aligned;"   ::: "memory");
}

extern "C" void kernel_launch(void* const* d_in, const int* in_sizes, int n_in,
                              void* d_out, int out_size) {
  const float* x  = (const float*)d_in[0];
  const float* Wf = (const float*)d_in[1];
  const float* Uf = (const float*)d_in[2];
  const float* bf = (const float*)d_in[3];
  const float* Wi = (const float*)d_in[4];
  const float* Ui = (const float*)d_in[5];
  const float* bi = (const float*)d_in[6];
  const float* Wo = (const float*)d_in[7];
  const float* Uo = (const float*)d_in[8];
  const float* bo = (const float*)d_in[9];
  const float* Wc = (const float*)d_in[10];
  const float* Uc = (const float*)d_in[11];
  const float* bc = (const float*)d_in[12];
  float* out = (float*)d_out;

  dim3 g1(512, 16);
  xw_gemm<<<g1, 256>>>(x, Wf, Wi, Wc, Wo, bf, bi, bc, bo);
  lstm_rec<<<128, 256>>>(Uf, Ui, Uc, Uo, out, out_size);
}

// round 15
// speedup vs baseline: 2.6805x; 2.6805x over previous
#include <cuda_runtime.h>

typedef unsigned long long ull;

#define S_LEN 2048
#define COLS 1024

__device__ float g_xg[(size_t)32 * S_LEN * COLS];   // [b*S+s][gate*256+j], gates f,i,c,o

__device__ __forceinline__ ull fma2(ull a, ull b, ull c){
  ull d; asm("fma.rn.f32x2 %0, %1, %2, %3;" : "=l"(d) : "l"(a), "l"(b), "l"(c)); return d;
}
__device__ __forceinline__ ull dup2(float x){
  ull d; asm("mov.b64 %0, {%1, %1};" : "=l"(d) : "f"(x)); return d;
}
__device__ __forceinline__ ull pack2(float lo, float hi){
  ull d; asm("mov.b64 %0, {%1, %2};" : "=l"(d) : "f"(lo), "f"(hi)); return d;
}
__device__ __forceinline__ void unpack2(ull v, float& lo, float& hi){
  asm("mov.b64 {%0, %1}, %2;" : "=f"(lo), "=f"(hi) : "l"(v));
}
// MUFU-only activations (tanh.approx: sm_75+; err ~1e-5 abs, fine for 1e-3 budget)
__device__ __forceinline__ float ftanh(float x){
  float y; asm("tanh.approx.f32 %0, %1;" : "=f"(y) : "f"(x)); return y;
}
__device__ __forceinline__ float fsig(float x){
  float t; asm("ex2.approx.f32 %0, %1;" : "=f"(t) : "f"(-x * 1.4426950408889634f));
  float r; asm("rcp.approx.f32 %0, %1;" : "=f"(r) : "f"(1.0f + t));
  return r;
}
__device__ __forceinline__ unsigned smem_u32(const void* p){
  unsigned a; asm("{ .reg .u64 t; cvta.to.shared.u64 t, %1; cvt.u32.u64 %0, t; }" : "=r"(a) : "l"(p));
  return a;
}
__device__ __forceinline__ void st_cluster_f32(unsigned laddr, unsigned rank, float v){
  asm volatile("{ .reg .b32 ra; mapa.shared::cluster.u32 ra, %0, %1; "
               "st.shared::cluster.f32 [ra], %2; }" :: "r"(laddr), "r"(rank), "f"(v) : "memory");
}

// ---------------- kernel 1: xg = x @ W + b (fp32x2 GEMM, 128x64x32 tiles) ----------------
__global__ __launch_bounds__(256, 2) void xw_gemm(
    const float* __restrict__ x,
    const float* __restrict__ Wf, const float* __restrict__ Wi,
    const float* __restrict__ Wc, const float* __restrict__ Wo,
    const float* __restrict__ bf, const float* __restrict__ bi,
    const float* __restrict__ bc, const float* __restrict__ bo)
{
  __shared__ float A_s[32][132];
  __shared__ float B_s[32][68];
  const int r0 = blockIdx.x * 128;
  const int c0 = blockIdx.y * 64;
  const int gate = c0 >> 8, j0 = c0 & 255;
  const float* Wg; const float* bg;
  if (gate == 0){ Wg = Wf; bg = bf; } else if (gate == 1){ Wg = Wi; bg = bi; }
  else if (gate == 2){ Wg = Wc; bg = bc; } else { Wg = Wo; bg = bo; }

  const int tid = threadIdx.x;
  const int tx = tid & 15, ty = tid >> 4;
  const int arow = tid >> 3, ak = (tid & 7) * 4;

  ull acc[4][4];
  #pragma unroll
  for (int i = 0; i < 4; i++)
    #pragma unroll
    for (int j = 0; j < 4; j++) acc[i][j] = 0ull;

  for (int kc = 0; kc < 256; kc += 32){
    #pragma unroll
    for (int i = 0; i < 4; i++){
      float4 v = *(const float4*)&x[(size_t)(r0 + arow + i*32) * 256 + kc + ak];
      A_s[ak+0][arow + i*32] = v.x; A_s[ak+1][arow + i*32] = v.y;
      A_s[ak+2][arow + i*32] = v.z; A_s[ak+3][arow + i*32] = v.w;
    }
    #pragma unroll
    for (int j = 0; j < 2; j++){
      int e = tid + j*256, kk = e >> 4, nn = (e & 15) * 4;
      *(float4*)&B_s[kk][nn] = *(const float4*)&Wg[(size_t)(kc + kk) * 256 + j0 + nn];
    }
    __syncthreads();
    #pragma unroll
    for (int k = 0; k < 32; k++){
      ulonglong2 a01 = *(const ulonglong2*)&A_s[k][ty*8];
      ulonglong2 a23 = *(const ulonglong2*)&A_s[k][ty*8 + 4];
      float4 bq = *(const float4*)&B_s[k][tx*4];
      ull bb0 = dup2(bq.x), bb1 = dup2(bq.y), bb2 = dup2(bq.z), bb3 = dup2(bq.w);
      ull av[4] = {a01.x, a01.y, a23.x, a23.y};
      #pragma unroll
      for (int i = 0; i < 4; i++){
        acc[i][0] = fma2(av[i], bb0, acc[i][0]);
        acc[i][1] = fma2(av[i], bb1, acc[i][1]);
        acc[i][2] = fma2(av[i], bb2, acc[i][2]);
        acc[i][3] = fma2(av[i], bb3, acc[i][3]);
      }
    }
    __syncthreads();
  }

  float bias[4];
  #pragma unroll
  for (int j = 0; j < 4; j++) bias[j] = bg[j0 + tx*4 + j];
  #pragma unroll
  for (int i = 0; i < 4; i++){
    float lo[4], hi[4];
    #pragma unroll
    for (int j = 0; j < 4; j++) unpack2(acc[i][j], lo[j], hi[j]);
    size_t base = (size_t)(r0 + ty*8 + 2*i) * COLS + c0 + tx*4;
    *(float4*)&g_xg[base]        = make_float4(lo[0]+bias[0], lo[1]+bias[1], lo[2]+bias[2], lo[3]+bias[3]);
    *(float4*)&g_xg[base + COLS] = make_float4(hi[0]+bias[0], hi[1]+bias[1], hi[2]+bias[2], hi[3]+bias[3]);
  }
}

// ---------------- kernel 2: clustered recurrence (R12 skeleton) ----------------
// 128 CTAs = 16 clusters x 8 CTAs, 2 batches/cluster. CTA owns units
// [r*32, r*32+32) x 4 gates; U register-resident. One cluster barrier per step.
// This round: MUFU activations, one-step-ahead xg prefetch issued into the
// barrier settle window, out-store moved off the pre-arrive path.
__global__ __launch_bounds__(256, 1) __cluster_dims__(8, 1, 1)
void lstm_rec(
    const float* __restrict__ Uf, const float* __restrict__ Ui,
    const float* __restrict__ Uc, const float* __restrict__ Uo,
    float* __restrict__ out, int out_size)
{
  __shared__ __align__(16) float h_s[2][2][256];   // [phase][batch][k]
  __shared__ __align__(16) float red[8 * 256];     // [k-slice][(g*32+u)*2 + b]

  const int tid = threadIdx.x;
  const int w = tid >> 5, lane = tid & 31;
  const int r   = blockIdx.x & 7;    // cluster rank
  const int grp = blockIdx.x >> 3;   // 0..15
  const int ju  = r * 32 + lane;     // owned unit (per gate)
  const int kb  = w * 32;            // owned k-chunk

  // U slice -> registers: ur[gate][jj] covers k in [kb+4jj, kb+4jj+4), col ju
  ulonglong2 ur[4][8];
  #pragma unroll
  for (int g = 0; g < 4; g++){
    const float* Ug = (g == 0) ? Uf : (g == 1) ? Ui : (g == 2) ? Uc : Uo;
    #pragma unroll
    for (int jj = 0; jj < 8; jj++){
      int k0 = kb + jj * 4;
      float a0 = __ldg(&Ug[(size_t)(k0 + 0) * 256 + ju]);
      float a1 = __ldg(&Ug[(size_t)(k0 + 1) * 256 + ju]);
      float a2 = __ldg(&Ug[(size_t)(k0 + 2) * 256 + ju]);
      float a3 = __ldg(&Ug[(size_t)(k0 + 3) * 256 + ju]);
      ur[g][jj].x = pack2(a0, a1);
      ur[g][jj].y = pack2(a2, a3);
    }
  }

  // zero both h buffers
  for (int e = tid; e < 2 * 2 * 256; e += 256) ((float*)h_s)[e] = 0.f;
  __syncthreads();

  const unsigned hs_base = smem_u32(h_s);
  const int b_g = tid >> 5;                 // gate-thread batch (tid<64)
  const int gb = grp * 2 + b_g;
  float cst = 0.f, hlast = 0.f;

  // preload xg for s=0
  float xc0, xc1, xc2, xc3;
  if (tid < 64){
    const float* xp = &g_xg[((size_t)gb * S_LEN) * COLS + ju];
    xc0 = __ldg(xp); xc1 = __ldg(xp + 256); xc2 = __ldg(xp + 512); xc3 = __ldg(xp + 768);
  }
  asm volatile("barrier.cluster.arrive.aligned;" ::: "memory");

  for (int s = 0; s < S_LEN; s++){
    const int p = s & 1, pn = p ^ 1;

    asm volatile("barrier.cluster.wait.aligned;" ::: "memory");

    // matvec: 128 fma2/thread, h via broadcast LDS.128, U in registers
    ull acc[4][2];
    #pragma unroll
    for (int g = 0; g < 4; g++){ acc[g][0] = 0ull; acc[g][1] = 0ull; }
    #pragma unroll
    for (int jj = 0; jj < 8; jj++){
      ulonglong2 h0 = *(const ulonglong2*)&h_s[p][0][kb + jj*4];
      ulonglong2 h1 = *(const ulonglong2*)&h_s[p][1][kb + jj*4];
      #pragma unroll
      for (int g = 0; g < 4; g++){
        acc[g][0] = fma2(h0.x, ur[g][jj].x, acc[g][0]);
        acc[g][0] = fma2(h0.y, ur[g][jj].y, acc[g][0]);
        acc[g][1] = fma2(h1.x, ur[g][jj].x, acc[g][1]);
        acc[g][1] = fma2(h1.y, ur[g][jj].y, acc[g][1]);
      }
    }
    #pragma unroll
    for (int g = 0; g < 4; g++){
      float l0, u0, l1, u1;
      unpack2(acc[g][0], l0, u0);
      unpack2(acc[g][1], l1, u1);
      *(float2*)&red[w*256 + (g*32 + lane)*2] = make_float2(l0 + u0, l1 + u1);
    }
    __syncthreads();

    // gates: tid<64 = (batch b_g, unit lane); MUFU activations only
    if (tid < 64){
      float z0 = xc0, z1 = xc1, z2 = xc2, z3 = xc3;
      #pragma unroll
      for (int ww = 0; ww < 8; ww++){
        int base = ww*256 + lane*2 + b_g;
        z0 += red[base +   0];
        z1 += red[base +  64];
        z2 += red[base + 128];
        z3 += red[base + 192];
      }
      float f  = fsig(z0);
      float ii = fsig(z1);
      float gg = ftanh(z2);
      float oo = fsig(z3);
      cst = f * cst + ii * gg;
      hlast = oo * ftanh(cst);
      // push h into every cluster CTA's h_s[pn][b_g][ju]
      unsigned haddr = hs_base + (unsigned)(((pn*2 + b_g)*256 + ju) * 4);
      #pragma unroll
      for (int t = 0; t < 8; t++) st_cluster_f32(haddr, (unsigned)t, hlast);
    }
    asm volatile("barrier.cluster.arrive.aligned;" ::: "memory");

    // settle window: out store + next-step xg prefetch (both off the sync path)
    if (tid < 64){
      out[((size_t)gb * S_LEN + s) * 256 + ju] = hlast;
      int sn = (s + 1 < S_LEN) ? s + 1 : s;   // clamp: value unused on last iter
      const float* xp = &g_xg[((size_t)gb * S_LEN + sn) * COLS + ju];
      xc0 = __ldg(xp); xc1 = __ldg(xp + 256); xc2 = __ldg(xp + 512); xc3 = __ldg(xp + 768);
    }
  }
  asm volatile("barrier.cluster.wait.aligned;" ::: "memory");

  // final (h_T, c_T), appended after hidden_seq if the output carries them
  if (tid < 64 && out_size >= 16777216 + 16384){
    size_t base = (size_t)16777216 + (size_t)gb * 256 + ju;
    out[base]        = hlast;
    out[base + 8192] = cst;
  }
}

extern "C" void kernel_launch(void* const* d_in, const int* in_sizes, int n_in,
                              void* d_out, int out_size) {
  const float* x  = (const float*)d_in[0];
  const float* Wf = (const float*)d_in[1];
  const float* Uf = (const float*)d_in[2];
  const float* bf = (const float*)d_in[3];
  const float* Wi = (const float*)d_in[4];
  const float* Ui = (const float*)d_in[5];
  const float* bi = (const float*)d_in[6];
  const float* Wo = (const float*)d_in[7];
  const float* Uo = (const float*)d_in[8];
  const float* bo = (const float*)d_in[9];
  const float* Wc = (const float*)d_in[10];
  const float* Uc = (const float*)d_in[11];
  const float* bc = (const float*)d_in[12];
  float* out = (float*)d_out;

  dim3 g1(512, 16);
  xw_gemm<<<g1, 256>>>(x, Wf, Wi, Wc, Wo, bf, bi, bc, bo);
  lstm_rec<<<128, 256>>>(Uf, Ui, Uc, Uo, out, out_size);
}